// round 10
// baseline (speedup 1.0000x reference)
#include <cuda_runtime.h>
#include <cstdint>

#define N_NODES 50000
#define N_EDGES 800000
#define D 128
#define BN_EPS 1e-5f
#define TOTAL4 (N_NODES * D / 4)

// ---------------- scratch (no allocations allowed) ----------------
__device__ double g_sum[D];
__device__ double g_sumsq[D];
__device__ float  g_scale[D];
__device__ float  g_bias[D];
__device__ unsigned g_done;
__device__ unsigned g_ready;

// ---------------- K1: init out = (1+eps)*h*norm^2, zero flags (2 float4/thread) ----------------
__global__ void __launch_bounds__(256) k_init(
    const float* __restrict__ h, const float* __restrict__ norm,
    const float* __restrict__ eps_p, float* __restrict__ out)
{
    int i = blockIdx.x * blockDim.x + threadIdx.x;
    if (i < D) { g_sum[i] = 0.0; g_sumsq[i] = 0.0; }
    if (i == 0) { g_done = 0; g_ready = 0; }

    int i0 = 2 * i;
    if (i0 >= TOTAL4) return;
    float epsv = 1.0f + eps_p[0];

    int r0 = i0 >> 5;
    int r1 = (i0 + 1) >> 5;
    float n0 = __ldg(norm + r0);
    float n1 = __ldg(norm + r1);
    float s0 = epsv * n0 * n0;
    float s1 = epsv * n1 * n1;
    float4 a = ((const float4*)h)[i0];
    float4 b = ((const float4*)h)[i0 + 1];
    ((float4*)out)[i0]     = make_float4(a.x * s0, a.y * s0, a.z * s0, a.w * s0);
    ((float4*)out)[i0 + 1] = make_float4(b.x * s1, b.y * s1, b.z * s1, b.w * s1);
}

// ---------------- K2: edge scatter (4 edges per warp) ----------------
__global__ void __launch_bounds__(256) k_edges(
    const float* __restrict__ h, const float* __restrict__ norm,
    const int* __restrict__ src, const int* __restrict__ dst,
    float* __restrict__ out)
{
    long long t = (long long)blockIdx.x * blockDim.x + threadIdx.x;
    int w    = (int)(t >> 5);            // warp id = edge quad id
    int lane = (int)(t & 31);
    if (4 * w >= N_EDGES) return;        // N_EDGES % 4 == 0: all quads full

    int4 s4 = __ldg((const int4*)src + w);   // warp-uniform
    int4 d4 = __ldg((const int4*)dst + w);   // warp-uniform
    float w0 = __ldg(norm + s4.x) * __ldg(norm + d4.x);
    float w1 = __ldg(norm + s4.y) * __ldg(norm + d4.y);
    float w2 = __ldg(norm + s4.z) * __ldg(norm + d4.z);
    float w3 = __ldg(norm + s4.w) * __ldg(norm + d4.w);

    float4 a = __ldg((const float4*)(h + (size_t)s4.x * D) + lane);
    float4 b = __ldg((const float4*)(h + (size_t)s4.y * D) + lane);
    float4 c = __ldg((const float4*)(h + (size_t)s4.z * D) + lane);
    float4 d = __ldg((const float4*)(h + (size_t)s4.w * D) + lane);

    float4 va = make_float4(a.x * w0, a.y * w0, a.z * w0, a.w * w0);
    float4 vb = make_float4(b.x * w1, b.y * w1, b.z * w1, b.w * w1);
    float4 vc = make_float4(c.x * w2, c.y * w2, c.z * w2, c.w * w2);
    float4 vd = make_float4(d.x * w3, d.y * w3, d.z * w3, d.w * w3);

    float* p0 = out + (size_t)d4.x * D + lane * 4;
    float* p1 = out + (size_t)d4.y * D + lane * 4;
    float* p2 = out + (size_t)d4.z * D + lane * 4;
    float* p3 = out + (size_t)d4.w * D + lane * 4;
    asm volatile("red.global.add.v4.f32 [%0], {%1,%2,%3,%4};"
                 :: "l"(p0), "f"(va.x), "f"(va.y), "f"(va.z), "f"(va.w) : "memory");
    asm volatile("red.global.add.v4.f32 [%0], {%1,%2,%3,%4};"
                 :: "l"(p1), "f"(vb.x), "f"(vb.y), "f"(vb.z), "f"(vb.w) : "memory");
    asm volatile("red.global.add.v4.f32 [%0], {%1,%2,%3,%4};"
                 :: "l"(p2), "f"(vc.x), "f"(vc.y), "f"(vc.z), "f"(vc.w) : "memory");
    asm volatile("red.global.add.v4.f32 [%0], {%1,%2,%3,%4};"
                 :: "l"(p3), "f"(vd.x), "f"(vd.y), "f"(vd.z), "f"(vd.w) : "memory");
}

// ---------------- K3: fused stats + grid sync + BN apply + ReLU ----------------
// Persistent: grid = 592 blocks (148 SMs x 4, guaranteed co-resident by
// __launch_bounds__(256,4) => <=64 regs; GB300 has 152 SMs for margin).
#define FUSE_BLOCKS 592
#define CHUNK_ROWS 64
#define NCHUNKS ((N_NODES + CHUNK_ROWS - 1) / CHUNK_ROWS)   // 782
__global__ void __launch_bounds__(256, 4) k_stats_bn(
    const float* __restrict__ gamma, const float* __restrict__ beta,
    float* __restrict__ out)
{
    int c    = threadIdx.x & 127;
    int half = threadIdx.x >> 7;

    // ---- phase A: stats partials ----
    float lsum = 0.f, lsq = 0.f;
    for (int chunk = blockIdx.x; chunk < NCHUNKS; chunk += FUSE_BLOCKS) {
        int row0 = chunk * CHUNK_ROWS + half * (CHUNK_ROWS / 2);
#pragma unroll 8
        for (int r = 0; r < CHUNK_ROWS / 2; r++) {
            int row = row0 + r;
            if (row >= N_NODES) break;
            float v = __ldg(out + (size_t)row * D + c);
            lsum += v;
            lsq  += v * v;
        }
    }
    __shared__ float s_s[2][D];
    __shared__ float s_q[2][D];
    s_s[half][c] = lsum;
    s_q[half][c] = lsq;
    __syncthreads();
    if (threadIdx.x < D) {
        atomicAdd(&g_sum[threadIdx.x],
                  (double)(s_s[0][threadIdx.x] + s_s[1][threadIdx.x]));
        atomicAdd(&g_sumsq[threadIdx.x],
                  (double)(s_q[0][threadIdx.x] + s_q[1][threadIdx.x]));
    }

    // ---- last block finalizes scale/bias ----
    __threadfence();
    __syncthreads();
    __shared__ int s_last;
    if (threadIdx.x == 0)
        s_last = (atomicAdd(&g_done, 1u) == (unsigned)(FUSE_BLOCKS - 1));
    __syncthreads();
    if (s_last) {
        if (threadIdx.x < D) {
            int ch = threadIdx.x;
            double su  = __ldcg(&g_sum[ch]);
            double ssq = __ldcg(&g_sumsq[ch]);
            double mu  = su / (double)N_NODES;
            double var = ssq / (double)N_NODES - mu * mu;
            double rstd = 1.0 / sqrt(var + (double)BN_EPS);
            float sc = gamma[ch] * (float)rstd;
            g_scale[ch] = sc;
            g_bias[ch]  = beta[ch] - (float)mu * sc;
        }
        __syncthreads();
        __threadfence();
        if (threadIdx.x == 0) atomicExch(&g_ready, 1u);
    }

    // ---- grid-wide wait (all blocks co-resident) ----
    if (threadIdx.x == 0) {
        volatile unsigned* vr = &g_ready;
        while (*vr == 0u) __nanosleep(64);
    }
    __syncthreads();

    // ---- phase B: BN apply + ReLU ----
    __shared__ float4 s_sc4[D / 4];
    __shared__ float4 s_bi4[D / 4];
    if (threadIdx.x < D) {
        ((float*)s_sc4)[threadIdx.x] = __ldcg(&g_scale[threadIdx.x]);
        ((float*)s_bi4)[threadIdx.x] = __ldcg(&g_bias[threadIdx.x]);
    }
    __syncthreads();

    for (int i4 = blockIdx.x * 256 + threadIdx.x; i4 < TOTAL4;
         i4 += FUSE_BLOCKS * 256) {
        int c4 = i4 & (D / 4 - 1);
        float4 sc = s_sc4[c4];
        float4 bi = s_bi4[c4];
        float4 x = ((float4*)out)[i4];
        x.x = fmaxf(fmaf(x.x, sc.x, bi.x), 0.f);
        x.y = fmaxf(fmaf(x.y, sc.y, bi.y), 0.f);
        x.z = fmaxf(fmaf(x.z, sc.z, bi.z), 0.f);
        x.w = fmaxf(fmaf(x.w, sc.w, bi.w), 0.f);
        ((float4*)out)[i4] = x;
    }
}

// ---------------- launch ----------------
extern "C" void kernel_launch(void* const* d_in, const int* in_sizes, int n_in,
                              void* d_out, int out_size)
{
    const float* h     = (const float*)d_in[0];
    const float* norm  = (const float*)d_in[1];
    const float* eps   = (const float*)d_in[2];
    const float* gamma = (const float*)d_in[3];
    const float* beta  = (const float*)d_in[4];
    const int*   src   = (const int*)d_in[5];
    const int*   dst   = (const int*)d_in[6];
    float* out = (float*)d_out;

    (void)in_sizes; (void)n_in; (void)out_size;

    const int ipairs = (TOTAL4 + 1) / 2;
    k_init<<<(ipairs + 255) / 256, 256>>>(h, norm, eps, out);

    const long long ethreads = (long long)(N_EDGES / 4) * 32;
    k_edges<<<(unsigned)((ethreads + 255) / 256), 256>>>(h, norm, src, dst, out);

    k_stats_bn<<<FUSE_BLOCKS, 256>>>(gamma, beta, out);
}